// round 4
// baseline (speedup 1.0000x reference)
#include <cuda_runtime.h>
#include <cstdint>

#define NQ 14
#define D 16384
#define NROWS 8192          // BATCH*SEQ = 4*2048
#define R_PER_BLK 32
#define NBLK (NROWS / R_PER_BLK)   // 256
#define CHUNK 512
#define NCHUNK (D / CHUNK)         // 32
#define THREADS 512                // 256 compute + 256 zero-store
#define LOG2E_F 1.4426950408889634f

// FMA-only exp2: round-to-int via magic number, degree-5 poly on [-0.5,0.5],
// exponent inject via integer add. ~10 ops, no MUFU.
__device__ __forceinline__ float exp2_fast(float t) {
    const float MAGIC = 12582912.0f;          // 1.5 * 2^23
    float f = t + MAGIC;
    int   ib = __float_as_int(f);
    float r = t - (f - MAGIC);                // r in [-0.5, 0.5]
    float p = 1.3333558146428443e-3f;
    p = fmaf(p, r, 9.6181291076284772e-3f);
    p = fmaf(p, r, 5.5504108664821580e-2f);
    p = fmaf(p, r, 2.4022650695910072e-1f);
    p = fmaf(p, r, 6.9314718055994531e-1f);
    p = fmaf(p, r, 1.0f);
    return __int_as_float(__float_as_int(p) + (ib << 23));
}

// COMPLEX=1: out is interleaved complex64 (float2 per element), row stride D*8 B.
// COMPLEX=0: out is real float32, row stride D*4 B.
template<int COMPLEX>
__global__ __launch_bounds__(THREADS, 1)
void qenc_kernel(const float* __restrict__ x,     // [8192]
                 const float* __restrict__ rot,   // [14,3]
                 const float* __restrict__ ent,   // [13]
                 const float* __restrict__ W1,    // [14]
                 const float* __restrict__ b1,    // [14]
                 const float* __restrict__ W2,    // [14,16384] row-major
                 const float* __restrict__ b2,    // [16384]
                 float* __restrict__ out)
{
    __shared__ float h2[R_PER_BLK][NQ];
    __shared__ float e0s[R_PER_BLK];
    __shared__ float red[8][R_PER_BLK];
    __shared__ float2 total_s;

    const int tid  = threadIdx.x;
    const int row0 = blockIdx.x * R_PER_BLK;

    // --- scalar "total" (one store-side thread; tiny) ---
    if (tid == 256) {
        float tr = 1.f, ti = 0.f;
        #pragma unroll
        for (int q = 0; q < NQ; q++) {
            float a0 = rot[q*3+0]*0.5f, a1 = rot[q*3+1]*0.5f, a2 = rot[q*3+2]*0.5f;
            float fr = cosf(a0)*cosf(a1)*cosf(a2);
            float fi = sinf(a0)*sinf(a1)*sinf(a2);
            float nr = tr*fr - ti*fi, ni = tr*fi + ti*fr;
            tr = nr; ti = ni;
        }
        #pragma unroll
        for (int e = 0; e < NQ-1; e++) {
            float cs = 1.f/(1.f + expf(-ent[e]));
            float fr = cs, fi = 1.f - cs;
            float nr = tr*fr - ti*fi, ni = tr*fi + ti*fr;
            tr = nr; ti = ni;
        }
        total_s = make_float2(tr, ti);
    }
    if (tid < R_PER_BLK * NQ) {
        int r = tid / NQ, k = tid - r * NQ;
        h2[r][k] = tanhf(x[row0 + r] * W1[k] + b1[k]) * LOG2E_F;
    }
    __syncthreads();

    if (tid < 256) {
        // ================= compute path =================
        float acc[R_PER_BLK];
        #pragma unroll
        for (int r = 0; r < R_PER_BLK; r++) acc[r] = 0.f;

        for (int c = 0; c < NCHUNK; c++) {
            const int j0 = c * CHUNK + tid;
            const int j1 = j0 + 256;
            float w2a[NQ], w2b[NQ];
            #pragma unroll
            for (int k = 0; k < NQ; k++) {
                w2a[k] = W2[k * D + j0];
                w2b[k] = W2[k * D + j1];
            }
            const float bb0 = b2[j0] * LOG2E_F;
            const float bb1 = b2[j1] * LOG2E_F;
            const bool isc0 = (c == 0) && (tid == 0);

            #pragma unroll
            for (int r = 0; r < R_PER_BLK; r++) {
                float ta = bb0, tb = bb1;
                #pragma unroll
                for (int k = 0; k < NQ; k++) {
                    float h = h2[r][k];
                    ta = fmaf(h, w2a[k], ta);
                    tb = fmaf(h, w2b[k], tb);
                }
                float ea = exp2_fast(ta);
                float eb = exp2_fast(tb);
                acc[r] += ea + eb;
                if (isc0) e0s[r] = ea;
            }
        }
        const int lane = tid & 31, w = tid >> 5;
        #pragma unroll
        for (int r = 0; r < R_PER_BLK; r++) {
            float v = acc[r];
            v += __shfl_xor_sync(0xffffffffu, v, 16);
            v += __shfl_xor_sync(0xffffffffu, v, 8);
            v += __shfl_xor_sync(0xffffffffu, v, 4);
            v += __shfl_xor_sync(0xffffffffu, v, 2);
            v += __shfl_xor_sync(0xffffffffu, v, 1);
            if (lane == 0) red[w][r] = v;
        }
    } else {
        // ================= zero-store path =================
        // Per block: 32 rows * D elements * (8 or 4) bytes.
        const size_t row_f = (size_t)D * (COMPLEX ? 2 : 1);  // floats per row
        float4* dst = reinterpret_cast<float4*>(out + (size_t)row0 * row_f);
        const int n4 = (int)(R_PER_BLK * row_f / 4);
        const float4 z = make_float4(0.f, 0.f, 0.f, 0.f);
        for (int i = tid - 256; i < n4; i += 256) dst[i] = z;
    }
    __syncthreads();

    if (tid < R_PER_BLK) {
        float s = 0.f;
        #pragma unroll
        for (int w = 0; w < 8; w++) s += red[w][tid];
        float w0 = e0s[tid] / s;
        float2 t = total_s;
        const size_t row_f = (size_t)D * (COMPLEX ? 2 : 1);
        float* p = out + (size_t)(row0 + tid) * row_f;
        if (COMPLEX) { p[0] = t.x * w0; p[1] = t.y * w0; }
        else         { p[0] = t.x * w0; }
    }
}

// Safe fallback: zero exactly n_floats floats (4-byte stores, alignment-agnostic).
__global__ void zero_kernel(float* __restrict__ out, size_t n_floats)
{
    size_t i = (size_t)blockIdx.x * blockDim.x + threadIdx.x;
    const size_t stride = (size_t)gridDim.x * blockDim.x;
    for (; i < n_floats; i += stride) out[i] = 0.f;
}

extern "C" void kernel_launch(void* const* d_in, const int* in_sizes, int n_in,
                              void* d_out, int out_size) {
    // ---- bind inputs by size (elements OR bytes; union is collision-free) ----
    const float *x = 0, *rot = 0, *ent = 0, *W1 = 0, *b1 = 0, *W2 = 0, *b2 = 0;
    for (int i = 0; i < n_in; i++) {
        const float* p = (const float*)d_in[i];
        switch (in_sizes[i]) {
            case 8192: case 32768:    x   = p; break;
            case 42:   case 168:      rot = p; break;
            case 13:   case 52:       ent = p; break;
            case 229376: case 917504: W2  = p; break;
            case 16384:  case 65536:  b2  = p; break;
            case 14:   case 56:       if (!W1) W1 = p; else b1 = p; break;
            default: break;
        }
    }
    const bool bound = x && rot && ent && W1 && b1 && W2 && b2;
    const bool a16 = (((uintptr_t)d_out) & 15) == 0;

    // ---- derive output layout STRICTLY from out_size (never assume) ----
    // 268435456 floats  -> complex64 as interleaved float pairs, 1 GiB
    // 1073741824        -> byte count, 1 GiB, interleaved complex
    // 134217728         -> ambiguous; take the CONSERVATIVE (small) reading:
    //                      real float32 [B,S,D], 512 MiB. Cannot overrun.
    if ((out_size == 268435456 || out_size == 1073741824) && bound && a16) {
        qenc_kernel<1><<<NBLK, THREADS>>>(x, rot, ent, W1, b1, W2, b2,
                                          (float*)d_out);
    } else if (out_size == 134217728 && bound && a16) {
        qenc_kernel<0><<<NBLK, THREADS>>>(x, rot, ent, W1, b1, W2, b2,
                                          (float*)d_out);
    } else {
        // Unknown layout or binding failure: zero exactly out_size floats
        // under the documented "elements of output dtype" convention.
        // (Under-covers if elements are 8-byte — safe; clean rel_err signal.)
        size_t n_floats;
        if (out_size == 1073741824)      n_floats = (size_t)out_size / 4;
        else if (out_size == 268435456 ||
                 out_size == 134217728)  n_floats = (size_t)out_size;
        else                             n_floats = (size_t)(out_size > 0 ? out_size : 0);
        zero_kernel<<<1024, 256>>>((float*)d_out, n_floats);
    }
}